// round 13
// baseline (speedup 1.0000x reference)
#include <cuda_runtime.h>
#include <cuda_bf16.h>
#include <cstdint>

#define BB 8
#define HH 8
#define NN 16384
#define KSLOT 64
#define NSPL 16
#define CH 128
#define NITER 64
#define MLPR 8
#define QSCALE 0.18033688011112042f   // 0.125 * log2(e)

__device__ __nv_bfloat16 g_hits[(size_t)BB * NN * 256];
__device__ __nv_bfloat16 g_Wkvt[1024 * 256];
__device__ __nv_bfloat16 g_q[(size_t)BB * HH * 64 * 64];
__device__ float g_pm[BB * HH * 32 * 64];
__device__ float g_pl[BB * HH * 32 * 64];
__device__ float g_po[(size_t)BB * HH * 32 * 64 * 64];

struct __align__(16) FS {
    __nv_bfloat16 Hs[128 * 264];     // 67584
    __nv_bfloat16 Wks[64 * 264];     // 33792
    __nv_bfloat16 Wvs[64 * 264];     // 33792
    __nv_bfloat16 Ks[128 * 72];      // 18432
    __nv_bfloat16 Vs[128 * 72];      // 18432
};                                    // 172032 B

__device__ __forceinline__ uint32_t smaddr(const void* p) {
    return (uint32_t)__cvta_generic_to_shared(p);
}
__device__ __forceinline__ void ldsm4(uint32_t* r, const void* p) {
    uint32_t a = smaddr(p);
    asm volatile("ldmatrix.sync.aligned.m8n8.x4.shared.b16 {%0,%1,%2,%3},[%4];"
                 : "=r"(r[0]), "=r"(r[1]), "=r"(r[2]), "=r"(r[3]) : "r"(a));
}
__device__ __forceinline__ void ldsm4t(uint32_t* r, const void* p) {
    uint32_t a = smaddr(p);
    asm volatile("ldmatrix.sync.aligned.m8n8.x4.trans.shared.b16 {%0,%1,%2,%3},[%4];"
                 : "=r"(r[0]), "=r"(r[1]), "=r"(r[2]), "=r"(r[3]) : "r"(a));
}
__device__ __forceinline__ void mma16816(float* c, const uint32_t* a, uint32_t b0, uint32_t b1) {
    asm volatile("mma.sync.aligned.m16n8k16.row.col.f32.bf16.bf16.f32 "
                 "{%0,%1,%2,%3},{%4,%5,%6,%7},{%8,%9},{%0,%1,%2,%3};"
                 : "+f"(c[0]), "+f"(c[1]), "+f"(c[2]), "+f"(c[3])
                 : "r"(a[0]), "r"(a[1]), "r"(a[2]), "r"(a[3]), "r"(b0), "r"(b1));
}
__device__ __forceinline__ void cpasync16(void* dst, const void* src) {
    uint32_t d = smaddr(dst);
    asm volatile("cp.async.ca.shared.global [%0],[%1],16;" :: "r"(d), "l"(src) : "memory");
}
__device__ __forceinline__ void cpcommit() { asm volatile("cp.async.commit_group;" ::: "memory"); }
__device__ __forceinline__ void cpwait0()  { asm volatile("cp.async.wait_group 0;" ::: "memory"); }
__device__ __forceinline__ uint32_t packbf(float a, float b) {
    __nv_bfloat162 t = __floats2bfloat162_rn(a, b);
    return *reinterpret_cast<uint32_t*>(&t);
}

// ===== prep: ln1_q j-split (bids 0-127) + W transpose (128-383) + cvt (384+) =====
__global__ void __launch_bounds__(256) prep_all(const float4* __restrict__ hits4,
                                                const float* __restrict__ Wk,
                                                const float* __restrict__ Wv,
                                                const float* __restrict__ slots,
                                                const float* __restrict__ g1,
                                                const float* __restrict__ be1,
                                                const float* __restrict__ Wq) {
    int bid = blockIdx.x, t = threadIdx.x;

    if (bid >= 384) {                        // ---- cvt hits: ILP4, full coverage
        size_t base = (size_t)(bid - 384) * 1024 + t;
        float4 v0 = hits4[base], v1 = hits4[base + 256],
               v2 = hits4[base + 512], v3 = hits4[base + 768];
        uint2* out2 = reinterpret_cast<uint2*>(g_hits) + base;
        out2[0]   = make_uint2(packbf(v0.x, v0.y), packbf(v0.z, v0.w));
        out2[256] = make_uint2(packbf(v1.x, v1.y), packbf(v1.z, v1.w));
        out2[512] = make_uint2(packbf(v2.x, v2.y), packbf(v2.z, v2.w));
        out2[768] = make_uint2(packbf(v3.x, v3.y), packbf(v3.z, v3.w));
        return;
    }
    if (bid >= 128) {                        // ---- W transpose via smem tile
        __shared__ float tile[32][33];
        int tileid = bid - 128;              // 0..255
        int mat = tileid >> 7; tileid &= 127;
        int j0 = (tileid & 15) * 32, k0 = (tileid >> 4) * 32;
        const float* W = mat ? Wv : Wk;
        int tx = t & 31, ty = t >> 5;
#pragma unroll
        for (int r = 0; r < 4; r++) {
            int kl = ty + r * 8;
            tile[kl][tx] = W[(size_t)(k0 + kl) * 512 + j0 + tx];
        }
        __syncthreads();
#pragma unroll
        for (int r = 0; r < 4; r++) {
            int jl = ty + r * 8;
            g_Wkvt[(size_t)(mat * 512 + j0 + jl) * 256 + k0 + tx] =
                __float2bfloat16(tile[tx][jl]);
        }
        return;
    }
    // ---- ln1 + Q projection, j-split: block = 8 rows x 256 q-cols ----
    __shared__ float xs[8][256];
    int lane = t & 31, w = t >> 5;
    int rg = bid >> 1, jh = bid & 1;
    int r0 = rg * 8;
    {
        int row = r0 + w;
        float v[8];
        float sum = 0.f;
#pragma unroll
        for (int i = 0; i < 8; i++) { v[i] = slots[(size_t)row * 256 + lane + 32 * i]; sum += v[i]; }
#pragma unroll
        for (int off = 16; off; off >>= 1) sum += __shfl_xor_sync(0xffffffffu, sum, off);
        float mean = sum * (1.f / 256.f);
        float vs = 0.f;
#pragma unroll
        for (int i = 0; i < 8; i++) { float d = v[i] - mean; vs += d * d; }
#pragma unroll
        for (int off = 16; off; off >>= 1) vs += __shfl_xor_sync(0xffffffffu, vs, off);
        float inv = rsqrtf(vs * (1.f / 256.f) + 1e-5f);
#pragma unroll
        for (int i = 0; i < 8; i++) {
            int c = lane + 32 * i;
            xs[w][c] = (v[i] - mean) * inv * g1[c] + be1[c];
        }
    }
    __syncthreads();
    int j = jh * 256 + t;
    float acc[8] = {};
    for (int kk0 = 0; kk0 < 256; kk0 += 8) {
        float wv[8];
#pragma unroll
        for (int u = 0; u < 8; u++) wv[u] = Wq[(kk0 + u) * 512 + j];
#pragma unroll
        for (int u = 0; u < 8; u++)
#pragma unroll
            for (int r = 0; r < 8; r++) acc[r] += xs[r][kk0 + u] * wv[u];
    }
    int h0 = j >> 6, d0 = j & 63;
#pragma unroll
    for (int r = 0; r < 8; r++) {
        int row = r0 + r, b = row >> 6, k = row & 63;
        g_q[(((size_t)b * HH + h0) * 64 + k) * 64 + d0] = __float2bfloat16(acc[r] * QSCALE);
    }
}

// ======= fused: KV-projection + flash attention (2 barriers/chunk) =======
__global__ void __launch_bounds__(256, 1) fused_attn() {
    extern __shared__ char smraw[];
    FS& sm = *reinterpret_cast<FS*>(smraw);

    const int s = blockIdx.x, b = blockIdx.y;
    const int tid = threadIdx.x, lane = tid & 31, warp = tid >> 5;
    const int wm = (warp >> 1) * 32, wn = (warp & 1) * 32;  // projection tiling
    const int p = warp & 3, hf = warp >> 2;                  // attention tiling
    const int g = lane >> 2, t4 = lane & 3;
    const size_t cta_row0 = (size_t)b * NN + (size_t)s * (NN / NSPL);

    auto issueH = [&](int c) {
        const __nv_bfloat16* src = g_hits + (cta_row0 + (size_t)c * CH) * 256;
#pragma unroll
        for (int i = 0; i < 16; i++) {
            int idx = tid + 256 * i;
            int row = idx >> 5, seg = (idx & 31) * 8;
            cpasync16(sm.Hs + row * 264 + seg, src + (size_t)row * 256 + seg);
        }
        cpcommit();
    };
    auto issueW = [&](int h) {
#pragma unroll
        for (int i = 0; i < 8; i++) {
            int idx = tid + 256 * i;
            int row = idx >> 5, seg = (idx & 31) * 8;
            cpasync16(sm.Wks + row * 264 + seg, g_Wkvt + (size_t)(h * 64 + row) * 256 + seg);
            cpasync16(sm.Wvs + row * 264 + seg, g_Wkvt + (size_t)(512 + h * 64 + row) * 256 + seg);
        }
        cpcommit();
    };

    issueW(0);
    issueH(0);

    float mrow[2], lrow[2], oacc[8][4];
    uint32_t qa[4][4];

    for (int i = 0; i < NITER; i++) {
        const int h = i >> 3, c = i & 7;
        const int bh = b * HH + h;

        cpwait0();
        __syncthreads();                         // (1) H/W ready; prev attn done with KV

        // -------- projection: [K|V][128x64] = H[128x256] @ W^T --------
        float kacc[2][4][4] = {}, vacc[2][4][4] = {};
#pragma unroll
        for (int ks = 0; ks < 16; ks++) {
            uint32_t af[2][4];
#pragma unroll
            for (int mi = 0; mi < 2; mi++)
                ldsm4(af[mi], sm.Hs + (wm + mi * 16 + (lane & 15)) * 264 + ks * 16 + (lane >> 4) * 8);
#pragma unroll
            for (int nb = 0; nb < 2; nb++) {
                int nrow = wn + nb * 16 + (lane & 7) + ((lane >> 4) << 3);
                uint32_t bf[4], cf[4];
                ldsm4(bf, sm.Wks + nrow * 264 + ks * 16 + (lane & 8));
                mma16816(kacc[0][2 * nb],     af[0], bf[0], bf[1]);
                mma16816(kacc[0][2 * nb + 1], af[0], bf[2], bf[3]);
                mma16816(kacc[1][2 * nb],     af[1], bf[0], bf[1]);
                mma16816(kacc[1][2 * nb + 1], af[1], bf[2], bf[3]);
                ldsm4(cf, sm.Wvs + nrow * 264 + ks * 16 + (lane & 8));
                mma16816(vacc[0][2 * nb],     af[0], cf[0], cf[1]);
                mma16816(vacc[0][2 * nb + 1], af[0], cf[2], cf[3]);
                mma16816(vacc[1][2 * nb],     af[1], cf[0], cf[1]);
                mma16816(vacc[1][2 * nb + 1], af[1], cf[2], cf[3]);
            }
        }

        // epilogue -> bf16 K/V smem tiles (scalar STS.32: conflict-free banks 4g+t4)
#pragma unroll
        for (int mi = 0; mi < 2; mi++) {
            int row = wm + mi * 16 + g;
#pragma unroll
            for (int nj = 0; nj < 4; nj++) {
                int col = wn + nj * 8 + 2 * t4;
                *(uint32_t*)&sm.Ks[row * 72 + col]       = packbf(kacc[mi][nj][0], kacc[mi][nj][1]);
                *(uint32_t*)&sm.Ks[(row + 8) * 72 + col] = packbf(kacc[mi][nj][2], kacc[mi][nj][3]);
                *(uint32_t*)&sm.Vs[row * 72 + col]       = packbf(vacc[mi][nj][0], vacc[mi][nj][1]);
                *(uint32_t*)&sm.Vs[(row + 8) * 72 + col] = packbf(vacc[mi][nj][2], vacc[mi][nj][3]);
            }
        }
        __syncthreads();                         // (2) proj reads done + KV visible

        if (i + 1 < NITER) {                     // overlaps attention below
            if (c == 7) issueW(h + 1);
            issueH((c == 7) ? 0 : c + 1);
        }

        if (c == 0) {                            // Q frags direct from gmem; reset state
            const uint32_t* qp = (const uint32_t*)(g_q + (size_t)bh * 4096);
            int rq = p * 16 + g;
#pragma unroll
            for (int ks = 0; ks < 4; ks++) {
                int cb = ks * 16 + t4 * 2;
                qa[ks][0] = qp[(rq * 64 + cb) >> 1];
                qa[ks][1] = qp[((rq + 8) * 64 + cb) >> 1];
                qa[ks][2] = qp[(rq * 64 + cb + 8) >> 1];
                qa[ks][3] = qp[((rq + 8) * 64 + cb + 8) >> 1];
            }
            mrow[0] = mrow[1] = -1e30f;
            lrow[0] = lrow[1] = 0.f;
#pragma unroll
            for (int dt = 0; dt < 8; dt++)
#pragma unroll
                for (int r = 0; r < 4; r++) oacc[dt][r] = 0.f;
        }

        // -------- attention: QK^T over this warp's n-half --------
        float sacc[8][4] = {};
#pragma unroll
        for (int ks = 0; ks < 4; ks++) {
#pragma unroll
            for (int np = 0; np < 4; np++) {
                int nrow = hf * 64 + np * 16 + (lane & 7) + ((lane >> 4) << 3);
                uint32_t bf[4];
                ldsm4(bf, sm.Ks + nrow * 72 + ks * 16 + (lane & 8));
                mma16816(sacc[2 * np],     qa[ks], bf[0], bf[1]);
                mma16816(sacc[2 * np + 1], qa[ks], bf[2], bf[3]);
            }
        }
        // -------- independent in-warp online softmax (log2 domain) --------
#pragma unroll
        for (int r = 0; r < 2; r++) {
            float m = -1e30f;
#pragma unroll
            for (int nt = 0; nt < 8; nt++)
                m = fmaxf(m, fmaxf(sacc[nt][2 * r], sacc[nt][2 * r + 1]));
            m = fmaxf(m, __shfl_xor_sync(0xffffffffu, m, 1));
            m = fmaxf(m, __shfl_xor_sync(0xffffffffu, m, 2));
            float mnew = fmaxf(mrow[r], m);
            float sc = exp2f(mrow[r] - mnew);
            mrow[r] = mnew;
            float sum = 0.f;
#pragma unroll
            for (int nt = 0; nt < 8; nt++) {
                float p0 = exp2f(sacc[nt][2 * r] - mnew);
                float p1 = exp2f(sacc[nt][2 * r + 1] - mnew);
                sacc[nt][2 * r] = p0; sacc[nt][2 * r + 1] = p1;
                sum += p0 + p1;
            }
            sum += __shfl_xor_sync(0xffffffffu, sum, 1);
            sum += __shfl_xor_sync(0xffffffffu, sum, 2);
            lrow[r] = lrow[r] * sc + sum;
#pragma unroll
            for (int dt = 0; dt < 8; dt++) {
                oacc[dt][2 * r] *= sc; oacc[dt][2 * r + 1] *= sc;
            }
        }
        // -------- P @ V over this n-half --------
        uint32_t pf[4][4];
#pragma unroll
        for (int k2 = 0; k2 < 4; k2++) {
            pf[k2][0] = packbf(sacc[2 * k2][0],     sacc[2 * k2][1]);
            pf[k2][1] = packbf(sacc[2 * k2][2],     sacc[2 * k2][3]);
            pf[k2][2] = packbf(sacc[2 * k2 + 1][0], sacc[2 * k2 + 1][1]);
            pf[k2][3] = packbf(sacc[2 * k2 + 1][2], sacc[2 * k2 + 1][3]);
        }
#pragma unroll
        for (int k2 = 0; k2 < 4; k2++) {
#pragma unroll
            for (int dp = 0; dp < 4; dp++) {
                uint32_t vf[4];
                ldsm4t(vf, sm.Vs + (hf * 64 + k2 * 16 + (lane & 15)) * 72
                            + dp * 16 + (lane >> 4) * 8);
                mma16816(oacc[2 * dp],     pf[k2], vf[0], vf[1]);
                mma16816(oacc[2 * dp + 1], pf[k2], vf[2], vf[3]);
            }
        }

        // -------- head end: each hf half writes its OWN split partial --------
        if (c == 7) {
            const int base = (bh * 32 + hf * 16 + s) * 64;
            const int r0 = p * 16 + g;
#pragma unroll
            for (int dt = 0; dt < 8; dt++) {
                int col = dt * 8 + 2 * t4;
                *(float2*)&g_po[(size_t)(base + r0) * 64 + col] =
                    make_float2(oacc[dt][0], oacc[dt][1]);
                *(float2*)&g_po[(size_t)(base + r0 + 8) * 64 + col] =
                    make_float2(oacc[dt][2], oacc[dt][3]);
            }
            if (t4 == 0) {
                g_pm[base + r0] = mrow[0]; g_pm[base + r0 + 8] = mrow[1];
                g_pl[base + r0] = lrow[0]; g_pl[base + r0 + 8] = lrow[1];
            }
        }
    }
}

// ================= combine(32 splits) + MLP + residual + LN2 =====================
__global__ void __launch_bounds__(256) mlp_ln2(const float* __restrict__ slots,
                                               const float* __restrict__ W1,
                                               const float* __restrict__ b1,
                                               const float* __restrict__ W2,
                                               const float* __restrict__ b2,
                                               const float* __restrict__ g2,
                                               const float* __restrict__ be2,
                                               float* __restrict__ out) {
    __shared__ float av[MLPR][512];
    __shared__ float hid[MLPR][512];
    __shared__ float red[256];
    int t = threadIdx.x;
    int r0 = blockIdx.x * MLPR;
#pragma unroll
    for (int r = 0; r < MLPR; r++) {
        int row = r0 + r, bB = row >> 6, kk = row & 63;
#pragma unroll
        for (int jj = 0; jj < 2; jj++) {
            int d = t + 256 * jj;
            int h = d >> 6, dd = d & 63;
            int bh = bB * 8 + h;
            float M = -1e30f;
#pragma unroll
            for (int ss = 0; ss < 32; ss++)
                M = fmaxf(M, g_pm[(bh * 32 + ss) * 64 + kk]);
            float L = 0.f, acc = 0.f;
#pragma unroll
            for (int ss = 0; ss < 32; ss++) {
                int idx = (bh * 32 + ss) * 64 + kk;
                float w = exp2f(g_pm[idx] - M);
                L   += g_pl[idx] * w;
                acc += g_po[(size_t)idx * 64 + dd] * w;
            }
            av[r][d] = acc / L;
        }
    }
    __syncthreads();
    float a0[MLPR], a1[MLPR];
    float bb0 = b1[t], bb1 = b1[t + 256];
#pragma unroll
    for (int r = 0; r < MLPR; r++) { a0[r] = bb0; a1[r] = bb1; }
    for (int kk0 = 0; kk0 < 512; kk0 += 4) {
        float w0v[4], w1v[4];
#pragma unroll
        for (int u = 0; u < 4; u++) {
            w0v[u] = W1[(kk0 + u) * 512 + t];
            w1v[u] = W1[(kk0 + u) * 512 + t + 256];
        }
#pragma unroll
        for (int u = 0; u < 4; u++)
#pragma unroll
            for (int r = 0; r < MLPR; r++) {
                float x = av[r][kk0 + u];
                a0[r] += x * w0v[u]; a1[r] += x * w1v[u];
            }
    }
#pragma unroll
    for (int r = 0; r < MLPR; r++) {
        hid[r][t] = fmaxf(a0[r], 0.f);
        hid[r][t + 256] = fmaxf(a1[r], 0.f);
    }
    __syncthreads();
    float o[MLPR];
    float c0 = b2[t];
#pragma unroll
    for (int r = 0; r < MLPR; r++) o[r] = c0;
    for (int kk0 = 0; kk0 < 512; kk0 += 4) {
        float wv[4];
#pragma unroll
        for (int u = 0; u < 4; u++) wv[u] = W2[(kk0 + u) * 256 + t];
#pragma unroll
        for (int u = 0; u < 4; u++)
#pragma unroll
            for (int r = 0; r < MLPR; r++) o[r] += hid[r][kk0 + u] * wv[u];
    }
    float gg = g2[t], bbn = be2[t];
    for (int r = 0; r < MLPR; r++) {
        float x = slots[(size_t)(r0 + r) * 256 + t] + o[r];
        red[t] = x; __syncthreads();
        for (int off = 128; off; off >>= 1) { if (t < off) red[t] += red[t + off]; __syncthreads(); }
        float mean = red[0] * (1.f / 256.f); __syncthreads();
        float d = x - mean;
        red[t] = d * d; __syncthreads();
        for (int off = 128; off; off >>= 1) { if (t < off) red[t] += red[t + off]; __syncthreads(); }
        float var = red[0] * (1.f / 256.f); __syncthreads();
        out[(size_t)(r0 + r) * 256 + t] = d * rsqrtf(var + 1e-5f) * gg + bbn;
    }
}

extern "C" void kernel_launch(void* const* d_in, const int* in_sizes, int n_in,
                              void* d_out, int out_size) {
    const float* slots = (const float*)d_in[0];
    const float* hits  = (const float*)d_in[1];
    const float* ln1g  = (const float*)d_in[2];
    const float* ln1b  = (const float*)d_in[3];
    const float* Wq    = (const float*)d_in[4];
    const float* Wk    = (const float*)d_in[5];
    const float* Wv    = (const float*)d_in[6];
    const float* W1    = (const float*)d_in[7];
    const float* b1    = (const float*)d_in[8];
    const float* W2    = (const float*)d_in[9];
    const float* b2    = (const float*)d_in[10];
    const float* ln2g  = (const float*)d_in[11];
    const float* ln2b  = (const float*)d_in[12];
    float* out = (float*)d_out;

    cudaFuncSetAttribute(fused_attn, cudaFuncAttributeMaxDynamicSharedMemorySize,
                         (int)sizeof(FS));
    // grid: 128 ln1_q (j-split) + 256 transpose + 8192 cvt
    prep_all<<<8576, 256>>>((const float4*)hits, Wk, Wv, slots, ln1g, ln1b, Wq);
    fused_attn<<<dim3(NSPL, BB), 256, sizeof(FS)>>>();
    mlp_ln2<<<BB * KSLOT / MLPR, 256>>>(slots, W1, b1, W2, b2, ln2g, ln2b, out);
}

// round 14
// speedup vs baseline: 1.2029x; 1.2029x over previous
#include <cuda_runtime.h>
#include <cuda_bf16.h>
#include <cstdint>

#define BB 8
#define HH 8
#define NN 16384
#define KSLOT 64
#define NSPL 16
#define CH 128
#define NITER 64
#define MLPR 4
#define QSCALE 0.18033688011112042f   // 0.125 * log2(e)

__device__ __nv_bfloat16 g_hits[(size_t)BB * NN * 256];
__device__ __nv_bfloat16 g_Wkvt[1024 * 256];
__device__ __nv_bfloat16 g_q[(size_t)BB * HH * 64 * 64];
__device__ float g_pm[BB * HH * 32 * 64];
__device__ float g_pl[BB * HH * 32 * 64];
__device__ float g_po[(size_t)BB * HH * 32 * 64 * 64];

struct __align__(16) FS {
    __nv_bfloat16 Hs[128 * 264];     // 67584
    __nv_bfloat16 Wks[64 * 264];     // 33792
    __nv_bfloat16 Wvs[64 * 264];     // 33792
    __nv_bfloat16 Ks[128 * 72];      // 18432
    __nv_bfloat16 Vs[128 * 72];      // 18432
};                                    // 172032 B

__device__ __forceinline__ uint32_t smaddr(const void* p) {
    return (uint32_t)__cvta_generic_to_shared(p);
}
__device__ __forceinline__ void ldsm4(uint32_t* r, const void* p) {
    uint32_t a = smaddr(p);
    asm volatile("ldmatrix.sync.aligned.m8n8.x4.shared.b16 {%0,%1,%2,%3},[%4];"
                 : "=r"(r[0]), "=r"(r[1]), "=r"(r[2]), "=r"(r[3]) : "r"(a));
}
__device__ __forceinline__ void ldsm4t(uint32_t* r, const void* p) {
    uint32_t a = smaddr(p);
    asm volatile("ldmatrix.sync.aligned.m8n8.x4.trans.shared.b16 {%0,%1,%2,%3},[%4];"
                 : "=r"(r[0]), "=r"(r[1]), "=r"(r[2]), "=r"(r[3]) : "r"(a));
}
__device__ __forceinline__ void mma16816(float* c, const uint32_t* a, uint32_t b0, uint32_t b1) {
    asm volatile("mma.sync.aligned.m16n8k16.row.col.f32.bf16.bf16.f32 "
                 "{%0,%1,%2,%3},{%4,%5,%6,%7},{%8,%9},{%0,%1,%2,%3};"
                 : "+f"(c[0]), "+f"(c[1]), "+f"(c[2]), "+f"(c[3])
                 : "r"(a[0]), "r"(a[1]), "r"(a[2]), "r"(a[3]), "r"(b0), "r"(b1));
}
__device__ __forceinline__ void cpasync16(void* dst, const void* src) {
    uint32_t d = smaddr(dst);
    asm volatile("cp.async.ca.shared.global [%0],[%1],16;" :: "r"(d), "l"(src) : "memory");
}
__device__ __forceinline__ void cpcommit() { asm volatile("cp.async.commit_group;" ::: "memory"); }
__device__ __forceinline__ void cpwait0()  { asm volatile("cp.async.wait_group 0;" ::: "memory"); }
__device__ __forceinline__ uint32_t packbf(float a, float b) {
    __nv_bfloat162 t = __floats2bfloat162_rn(a, b);
    return *reinterpret_cast<uint32_t*>(&t);
}

// ===== prep: ln1_q j-split (bids 0-127) + W transpose (128-383) + cvt (384+) =====
__global__ void __launch_bounds__(256) prep_all(const float4* __restrict__ hits4,
                                                const float* __restrict__ Wk,
                                                const float* __restrict__ Wv,
                                                const float* __restrict__ slots,
                                                const float* __restrict__ g1,
                                                const float* __restrict__ be1,
                                                const float* __restrict__ Wq) {
    int bid = blockIdx.x, t = threadIdx.x;

    if (bid >= 384) {                        // ---- cvt hits: ILP4, full coverage
        size_t base = (size_t)(bid - 384) * 1024 + t;
        float4 v0 = hits4[base], v1 = hits4[base + 256],
               v2 = hits4[base + 512], v3 = hits4[base + 768];
        uint2* out2 = reinterpret_cast<uint2*>(g_hits) + base;
        out2[0]   = make_uint2(packbf(v0.x, v0.y), packbf(v0.z, v0.w));
        out2[256] = make_uint2(packbf(v1.x, v1.y), packbf(v1.z, v1.w));
        out2[512] = make_uint2(packbf(v2.x, v2.y), packbf(v2.z, v2.w));
        out2[768] = make_uint2(packbf(v3.x, v3.y), packbf(v3.z, v3.w));
        return;
    }
    if (bid >= 128) {                        // ---- W transpose via smem tile
        __shared__ float tile[32][33];
        int tileid = bid - 128;              // 0..255
        int mat = tileid >> 7; tileid &= 127;
        int j0 = (tileid & 15) * 32, k0 = (tileid >> 4) * 32;
        const float* W = mat ? Wv : Wk;
        int tx = t & 31, ty = t >> 5;
#pragma unroll
        for (int r = 0; r < 4; r++) {
            int kl = ty + r * 8;
            tile[kl][tx] = W[(size_t)(k0 + kl) * 512 + j0 + tx];
        }
        __syncthreads();
#pragma unroll
        for (int r = 0; r < 4; r++) {
            int jl = ty + r * 8;
            g_Wkvt[(size_t)(mat * 512 + j0 + jl) * 256 + k0 + tx] =
                __float2bfloat16(tile[tx][jl]);
        }
        return;
    }
    // ---- ln1 + Q projection, j-split: block = 8 rows x 256 q-cols ----
    __shared__ float xs[8][256];
    int lane = t & 31, w = t >> 5;
    int rg = bid >> 1, jh = bid & 1;
    int r0 = rg * 8;
    {
        int row = r0 + w;
        float v[8];
        float sum = 0.f;
#pragma unroll
        for (int i = 0; i < 8; i++) { v[i] = slots[(size_t)row * 256 + lane + 32 * i]; sum += v[i]; }
#pragma unroll
        for (int off = 16; off; off >>= 1) sum += __shfl_xor_sync(0xffffffffu, sum, off);
        float mean = sum * (1.f / 256.f);
        float vs = 0.f;
#pragma unroll
        for (int i = 0; i < 8; i++) { float d = v[i] - mean; vs += d * d; }
#pragma unroll
        for (int off = 16; off; off >>= 1) vs += __shfl_xor_sync(0xffffffffu, vs, off);
        float inv = rsqrtf(vs * (1.f / 256.f) + 1e-5f);
#pragma unroll
        for (int i = 0; i < 8; i++) {
            int c = lane + 32 * i;
            xs[w][c] = (v[i] - mean) * inv * g1[c] + be1[c];
        }
    }
    __syncthreads();
    int j = jh * 256 + t;
    float acc[8] = {};
    for (int kk0 = 0; kk0 < 256; kk0 += 8) {
        float wv[8];
#pragma unroll
        for (int u = 0; u < 8; u++) wv[u] = Wq[(kk0 + u) * 512 + j];
#pragma unroll
        for (int u = 0; u < 8; u++)
#pragma unroll
            for (int r = 0; r < 8; r++) acc[r] += xs[r][kk0 + u] * wv[u];
    }
    int h0 = j >> 6, d0 = j & 63;
#pragma unroll
    for (int r = 0; r < 8; r++) {
        int row = r0 + r, b = row >> 6, k = row & 63;
        g_q[(((size_t)b * HH + h0) * 64 + k) * 64 + d0] = __float2bfloat16(acc[r] * QSCALE);
    }
}

// ======= fused: KV-projection + flash attention (2 barriers/chunk) =======
__global__ void __launch_bounds__(256, 1) fused_attn() {
    extern __shared__ char smraw[];
    FS& sm = *reinterpret_cast<FS*>(smraw);

    const int s = blockIdx.x, b = blockIdx.y;
    const int tid = threadIdx.x, lane = tid & 31, warp = tid >> 5;
    const int wm = (warp >> 1) * 32, wn = (warp & 1) * 32;  // projection tiling
    const int p = warp & 3, hf = warp >> 2;                  // attention tiling
    const int g = lane >> 2, t4 = lane & 3;
    const size_t cta_row0 = (size_t)b * NN + (size_t)s * (NN / NSPL);

    auto issueH = [&](int c) {
        const __nv_bfloat16* src = g_hits + (cta_row0 + (size_t)c * CH) * 256;
#pragma unroll
        for (int i = 0; i < 16; i++) {
            int idx = tid + 256 * i;
            int row = idx >> 5, seg = (idx & 31) * 8;
            cpasync16(sm.Hs + row * 264 + seg, src + (size_t)row * 256 + seg);
        }
        cpcommit();
    };
    auto issueW = [&](int h) {
#pragma unroll
        for (int i = 0; i < 8; i++) {
            int idx = tid + 256 * i;
            int row = idx >> 5, seg = (idx & 31) * 8;
            cpasync16(sm.Wks + row * 264 + seg, g_Wkvt + (size_t)(h * 64 + row) * 256 + seg);
            cpasync16(sm.Wvs + row * 264 + seg, g_Wkvt + (size_t)(512 + h * 64 + row) * 256 + seg);
        }
        cpcommit();
    };

    issueW(0);
    issueH(0);

    float mrow[2], lrow[2], oacc[8][4];
    uint32_t qa[4][4];

    for (int i = 0; i < NITER; i++) {
        const int h = i >> 3, c = i & 7;
        const int bh = b * HH + h;

        cpwait0();
        __syncthreads();                         // (1) H/W ready; prev attn done with KV

        // -------- projection: [K|V][128x64] = H[128x256] @ W^T --------
        float kacc[2][4][4] = {}, vacc[2][4][4] = {};
#pragma unroll
        for (int ks = 0; ks < 16; ks++) {
            uint32_t af[2][4];
#pragma unroll
            for (int mi = 0; mi < 2; mi++)
                ldsm4(af[mi], sm.Hs + (wm + mi * 16 + (lane & 15)) * 264 + ks * 16 + (lane >> 4) * 8);
#pragma unroll
            for (int nb = 0; nb < 2; nb++) {
                int nrow = wn + nb * 16 + (lane & 7) + ((lane >> 4) << 3);
                uint32_t bf[4], cf[4];
                ldsm4(bf, sm.Wks + nrow * 264 + ks * 16 + (lane & 8));
                mma16816(kacc[0][2 * nb],     af[0], bf[0], bf[1]);
                mma16816(kacc[0][2 * nb + 1], af[0], bf[2], bf[3]);
                mma16816(kacc[1][2 * nb],     af[1], bf[0], bf[1]);
                mma16816(kacc[1][2 * nb + 1], af[1], bf[2], bf[3]);
                ldsm4(cf, sm.Wvs + nrow * 264 + ks * 16 + (lane & 8));
                mma16816(vacc[0][2 * nb],     af[0], cf[0], cf[1]);
                mma16816(vacc[0][2 * nb + 1], af[0], cf[2], cf[3]);
                mma16816(vacc[1][2 * nb],     af[1], cf[0], cf[1]);
                mma16816(vacc[1][2 * nb + 1], af[1], cf[2], cf[3]);
            }
        }

        // epilogue -> bf16 K/V smem tiles (scalar STS.32: conflict-free banks 4g+t4)
#pragma unroll
        for (int mi = 0; mi < 2; mi++) {
            int row = wm + mi * 16 + g;
#pragma unroll
            for (int nj = 0; nj < 4; nj++) {
                int col = wn + nj * 8 + 2 * t4;
                *(uint32_t*)&sm.Ks[row * 72 + col]       = packbf(kacc[mi][nj][0], kacc[mi][nj][1]);
                *(uint32_t*)&sm.Ks[(row + 8) * 72 + col] = packbf(kacc[mi][nj][2], kacc[mi][nj][3]);
                *(uint32_t*)&sm.Vs[row * 72 + col]       = packbf(vacc[mi][nj][0], vacc[mi][nj][1]);
                *(uint32_t*)&sm.Vs[(row + 8) * 72 + col] = packbf(vacc[mi][nj][2], vacc[mi][nj][3]);
            }
        }
        __syncthreads();                         // (2) proj reads done + KV visible

        if (i + 1 < NITER) {                     // overlaps attention below
            if (c == 7) issueW(h + 1);
            issueH((c == 7) ? 0 : c + 1);
        }

        if (c == 0) {                            // Q frags direct from gmem; reset state
            const uint32_t* qp = (const uint32_t*)(g_q + (size_t)bh * 4096);
            int rq = p * 16 + g;
#pragma unroll
            for (int ks = 0; ks < 4; ks++) {
                int cb = ks * 16 + t4 * 2;
                qa[ks][0] = qp[(rq * 64 + cb) >> 1];
                qa[ks][1] = qp[((rq + 8) * 64 + cb) >> 1];
                qa[ks][2] = qp[(rq * 64 + cb + 8) >> 1];
                qa[ks][3] = qp[((rq + 8) * 64 + cb + 8) >> 1];
            }
            mrow[0] = mrow[1] = -1e30f;
            lrow[0] = lrow[1] = 0.f;
#pragma unroll
            for (int dt = 0; dt < 8; dt++)
#pragma unroll
                for (int r = 0; r < 4; r++) oacc[dt][r] = 0.f;
        }

        // -------- attention: QK^T over this warp's n-half --------
        float sacc[8][4] = {};
#pragma unroll
        for (int ks = 0; ks < 4; ks++) {
#pragma unroll
            for (int np = 0; np < 4; np++) {
                int nrow = hf * 64 + np * 16 + (lane & 7) + ((lane >> 4) << 3);
                uint32_t bf[4];
                ldsm4(bf, sm.Ks + nrow * 72 + ks * 16 + (lane & 8));
                mma16816(sacc[2 * np],     qa[ks], bf[0], bf[1]);
                mma16816(sacc[2 * np + 1], qa[ks], bf[2], bf[3]);
            }
        }
        // -------- independent in-warp online softmax (log2 domain) --------
#pragma unroll
        for (int r = 0; r < 2; r++) {
            float m = -1e30f;
#pragma unroll
            for (int nt = 0; nt < 8; nt++)
                m = fmaxf(m, fmaxf(sacc[nt][2 * r], sacc[nt][2 * r + 1]));
            m = fmaxf(m, __shfl_xor_sync(0xffffffffu, m, 1));
            m = fmaxf(m, __shfl_xor_sync(0xffffffffu, m, 2));
            float mnew = fmaxf(mrow[r], m);
            float sc = exp2f(mrow[r] - mnew);
            mrow[r] = mnew;
            float sum = 0.f;
#pragma unroll
            for (int nt = 0; nt < 8; nt++) {
                float p0 = exp2f(sacc[nt][2 * r] - mnew);
                float p1 = exp2f(sacc[nt][2 * r + 1] - mnew);
                sacc[nt][2 * r] = p0; sacc[nt][2 * r + 1] = p1;
                sum += p0 + p1;
            }
            sum += __shfl_xor_sync(0xffffffffu, sum, 1);
            sum += __shfl_xor_sync(0xffffffffu, sum, 2);
            lrow[r] = lrow[r] * sc + sum;
#pragma unroll
            for (int dt = 0; dt < 8; dt++) {
                oacc[dt][2 * r] *= sc; oacc[dt][2 * r + 1] *= sc;
            }
        }
        // -------- P @ V over this n-half --------
        uint32_t pf[4][4];
#pragma unroll
        for (int k2 = 0; k2 < 4; k2++) {
            pf[k2][0] = packbf(sacc[2 * k2][0],     sacc[2 * k2][1]);
            pf[k2][1] = packbf(sacc[2 * k2][2],     sacc[2 * k2][3]);
            pf[k2][2] = packbf(sacc[2 * k2 + 1][0], sacc[2 * k2 + 1][1]);
            pf[k2][3] = packbf(sacc[2 * k2 + 1][2], sacc[2 * k2 + 1][3]);
        }
#pragma unroll
        for (int k2 = 0; k2 < 4; k2++) {
#pragma unroll
            for (int dp = 0; dp < 4; dp++) {
                uint32_t vf[4];
                ldsm4t(vf, sm.Vs + (hf * 64 + k2 * 16 + (lane & 15)) * 72
                            + dp * 16 + (lane >> 4) * 8);
                mma16816(oacc[2 * dp],     pf[k2], vf[0], vf[1]);
                mma16816(oacc[2 * dp + 1], pf[k2], vf[2], vf[3]);
            }
        }

        // -------- head end: each hf half writes its OWN split partial --------
        if (c == 7) {
            const int base = (bh * 32 + hf * 16 + s) * 64;
            const int r0 = p * 16 + g;
#pragma unroll
            for (int dt = 0; dt < 8; dt++) {
                int col = dt * 8 + 2 * t4;
                *(float2*)&g_po[(size_t)(base + r0) * 64 + col] =
                    make_float2(oacc[dt][0], oacc[dt][1]);
                *(float2*)&g_po[(size_t)(base + r0 + 8) * 64 + col] =
                    make_float2(oacc[dt][2], oacc[dt][3]);
            }
            if (t4 == 0) {
                g_pm[base + r0] = mrow[0]; g_pm[base + r0 + 8] = mrow[1];
                g_pl[base + r0] = lrow[0]; g_pl[base + r0 + 8] = lrow[1];
            }
        }
    }
}

// ================= combine(32 splits) + MLP + residual + LN2 =====================
__global__ void __launch_bounds__(256) mlp_ln2(const float* __restrict__ slots,
                                               const float* __restrict__ W1,
                                               const float* __restrict__ b1,
                                               const float* __restrict__ W2,
                                               const float* __restrict__ b2,
                                               const float* __restrict__ g2,
                                               const float* __restrict__ be2,
                                               float* __restrict__ out) {
    __shared__ float av[MLPR][512];
    __shared__ float hid[MLPR][512];
    __shared__ float red[256];
    int t = threadIdx.x;
    int r0 = blockIdx.x * MLPR;
#pragma unroll
    for (int r = 0; r < MLPR; r++) {
        int row = r0 + r, bB = row >> 6, kk = row & 63;
#pragma unroll
        for (int jj = 0; jj < 2; jj++) {
            int d = t + 256 * jj;
            int h = d >> 6, dd = d & 63;
            int bh = bB * 8 + h;
            float M = -1e30f;
#pragma unroll
            for (int ss = 0; ss < 32; ss++)
                M = fmaxf(M, g_pm[(bh * 32 + ss) * 64 + kk]);
            float L = 0.f, acc = 0.f;
#pragma unroll
            for (int ss = 0; ss < 32; ss++) {
                int idx = (bh * 32 + ss) * 64 + kk;
                float w = exp2f(g_pm[idx] - M);
                L   += g_pl[idx] * w;
                acc += g_po[(size_t)idx * 64 + dd] * w;
            }
            av[r][d] = acc / L;
        }
    }
    __syncthreads();
    float a0[MLPR], a1[MLPR];
    float bb0 = b1[t], bb1 = b1[t + 256];
#pragma unroll
    for (int r = 0; r < MLPR; r++) { a0[r] = bb0; a1[r] = bb1; }
    for (int kk0 = 0; kk0 < 512; kk0 += 4) {
        float w0v[4], w1v[4];
#pragma unroll
        for (int u = 0; u < 4; u++) {
            w0v[u] = W1[(kk0 + u) * 512 + t];
            w1v[u] = W1[(kk0 + u) * 512 + t + 256];
        }
#pragma unroll
        for (int u = 0; u < 4; u++)
#pragma unroll
            for (int r = 0; r < MLPR; r++) {
                float x = av[r][kk0 + u];
                a0[r] += x * w0v[u]; a1[r] += x * w1v[u];
            }
    }
#pragma unroll
    for (int r = 0; r < MLPR; r++) {
        hid[r][t] = fmaxf(a0[r], 0.f);
        hid[r][t + 256] = fmaxf(a1[r], 0.f);
    }
    __syncthreads();
    float o[MLPR];
    float c0 = b2[t];
#pragma unroll
    for (int r = 0; r < MLPR; r++) o[r] = c0;
    for (int kk0 = 0; kk0 < 512; kk0 += 4) {
        float wv[4];
#pragma unroll
        for (int u = 0; u < 4; u++) wv[u] = W2[(kk0 + u) * 256 + t];
#pragma unroll
        for (int u = 0; u < 4; u++)
#pragma unroll
            for (int r = 0; r < MLPR; r++) o[r] += hid[r][kk0 + u] * wv[u];
    }
    float gg = g2[t], bbn = be2[t];
    for (int r = 0; r < MLPR; r++) {
        float x = slots[(size_t)(r0 + r) * 256 + t] + o[r];
        red[t] = x; __syncthreads();
        for (int off = 128; off; off >>= 1) { if (t < off) red[t] += red[t + off]; __syncthreads(); }
        float mean = red[0] * (1.f / 256.f); __syncthreads();
        float d = x - mean;
        red[t] = d * d; __syncthreads();
        for (int off = 128; off; off >>= 1) { if (t < off) red[t] += red[t + off]; __syncthreads(); }
        float var = red[0] * (1.f / 256.f); __syncthreads();
        out[(size_t)(r0 + r) * 256 + t] = d * rsqrtf(var + 1e-5f) * gg + bbn;
    }
}

extern "C" void kernel_launch(void* const* d_in, const int* in_sizes, int n_in,
                              void* d_out, int out_size) {
    const float* slots = (const float*)d_in[0];
    const float* hits  = (const float*)d_in[1];
    const float* ln1g  = (const float*)d_in[2];
    const float* ln1b  = (const float*)d_in[3];
    const float* Wq    = (const float*)d_in[4];
    const float* Wk    = (const float*)d_in[5];
    const float* Wv    = (const float*)d_in[6];
    const float* W1    = (const float*)d_in[7];
    const float* b1    = (const float*)d_in[8];
    const float* W2    = (const float*)d_in[9];
    const float* b2    = (const float*)d_in[10];
    const float* ln2g  = (const float*)d_in[11];
    const float* ln2b  = (const float*)d_in[12];
    float* out = (float*)d_out;

    cudaFuncSetAttribute(fused_attn, cudaFuncAttributeMaxDynamicSharedMemorySize,
                         (int)sizeof(FS));
    // grid: 128 ln1_q (j-split) + 256 transpose + 8192 cvt
    prep_all<<<8576, 256>>>((const float4*)hits, Wk, Wv, slots, ln1g, ln1b, Wq);
    fused_attn<<<dim3(NSPL, BB), 256, sizeof(FS)>>>();
    mlp_ln2<<<BB * KSLOT / MLPR, 256>>>(slots, W1, b1, W2, b2, ln2g, ln2b, out);
}

// round 15
// speedup vs baseline: 1.2625x; 1.0496x over previous
#include <cuda_runtime.h>
#include <cuda_bf16.h>
#include <cstdint>

#define BB 8
#define HH 8
#define NN 16384
#define KSLOT 64
#define NSPL 19            // 19 splits x 8 batches = 152 CTAs = full GB300
#define NPART 38           // partial splits per bh (2 hf halves x 19)
#define CH 128
#define MLPR 4
#define QSCALE 0.18033688011112042f   // 0.125 * log2(e)

__device__ __nv_bfloat16 g_hits[(size_t)BB * NN * 256];
__device__ __nv_bfloat16 g_Wkvt[1024 * 256];
__device__ __nv_bfloat16 g_q[(size_t)BB * HH * 64 * 64];
__device__ float g_pm[BB * HH * NPART * 64];
__device__ float g_pl[BB * HH * NPART * 64];
__device__ float g_po[(size_t)BB * HH * NPART * 64 * 64];

struct __align__(16) FS {
    __nv_bfloat16 Hs[128 * 264];     // 67584
    __nv_bfloat16 Wks[64 * 264];     // 33792
    __nv_bfloat16 Wvs[64 * 264];     // 33792
    __nv_bfloat16 Ks[128 * 72];      // 18432
    __nv_bfloat16 Vs[128 * 72];      // 18432
};                                    // 172032 B

__device__ __forceinline__ uint32_t smaddr(const void* p) {
    return (uint32_t)__cvta_generic_to_shared(p);
}
__device__ __forceinline__ void ldsm4(uint32_t* r, const void* p) {
    uint32_t a = smaddr(p);
    asm volatile("ldmatrix.sync.aligned.m8n8.x4.shared.b16 {%0,%1,%2,%3},[%4];"
                 : "=r"(r[0]), "=r"(r[1]), "=r"(r[2]), "=r"(r[3]) : "r"(a));
}
__device__ __forceinline__ void ldsm4t(uint32_t* r, const void* p) {
    uint32_t a = smaddr(p);
    asm volatile("ldmatrix.sync.aligned.m8n8.x4.trans.shared.b16 {%0,%1,%2,%3},[%4];"
                 : "=r"(r[0]), "=r"(r[1]), "=r"(r[2]), "=r"(r[3]) : "r"(a));
}
__device__ __forceinline__ void mma16816(float* c, const uint32_t* a, uint32_t b0, uint32_t b1) {
    asm volatile("mma.sync.aligned.m16n8k16.row.col.f32.bf16.bf16.f32 "
                 "{%0,%1,%2,%3},{%4,%5,%6,%7},{%8,%9},{%0,%1,%2,%3};"
                 : "+f"(c[0]), "+f"(c[1]), "+f"(c[2]), "+f"(c[3])
                 : "r"(a[0]), "r"(a[1]), "r"(a[2]), "r"(a[3]), "r"(b0), "r"(b1));
}
__device__ __forceinline__ void cpasync16(void* dst, const void* src) {
    uint32_t d = smaddr(dst);
    asm volatile("cp.async.ca.shared.global [%0],[%1],16;" :: "r"(d), "l"(src) : "memory");
}
__device__ __forceinline__ void cpcommit() { asm volatile("cp.async.commit_group;" ::: "memory"); }
__device__ __forceinline__ void cpwait0()  { asm volatile("cp.async.wait_group 0;" ::: "memory"); }
__device__ __forceinline__ uint32_t packbf(float a, float b) {
    __nv_bfloat162 t = __floats2bfloat162_rn(a, b);
    return *reinterpret_cast<uint32_t*>(&t);
}

// ===== prep: ln1_q j-split (bids 0-127) + W transpose (128-383) + cvt (384+) =====
__global__ void __launch_bounds__(256) prep_all(const float4* __restrict__ hits4,
                                                const float* __restrict__ Wk,
                                                const float* __restrict__ Wv,
                                                const float* __restrict__ slots,
                                                const float* __restrict__ g1,
                                                const float* __restrict__ be1,
                                                const float* __restrict__ Wq) {
    int bid = blockIdx.x, t = threadIdx.x;

    if (bid >= 384) {                        // ---- cvt hits: ILP4, full coverage
        size_t base = (size_t)(bid - 384) * 1024 + t;
        float4 v0 = hits4[base], v1 = hits4[base + 256],
               v2 = hits4[base + 512], v3 = hits4[base + 768];
        uint2* out2 = reinterpret_cast<uint2*>(g_hits) + base;
        out2[0]   = make_uint2(packbf(v0.x, v0.y), packbf(v0.z, v0.w));
        out2[256] = make_uint2(packbf(v1.x, v1.y), packbf(v1.z, v1.w));
        out2[512] = make_uint2(packbf(v2.x, v2.y), packbf(v2.z, v2.w));
        out2[768] = make_uint2(packbf(v3.x, v3.y), packbf(v3.z, v3.w));
        return;
    }
    if (bid >= 128) {                        // ---- W transpose via smem tile
        __shared__ float tile[32][33];
        int tileid = bid - 128;              // 0..255
        int mat = tileid >> 7; tileid &= 127;
        int j0 = (tileid & 15) * 32, k0 = (tileid >> 4) * 32;
        const float* W = mat ? Wv : Wk;
        int tx = t & 31, ty = t >> 5;
#pragma unroll
        for (int r = 0; r < 4; r++) {
            int kl = ty + r * 8;
            tile[kl][tx] = W[(size_t)(k0 + kl) * 512 + j0 + tx];
        }
        __syncthreads();
#pragma unroll
        for (int r = 0; r < 4; r++) {
            int jl = ty + r * 8;
            g_Wkvt[(size_t)(mat * 512 + j0 + jl) * 256 + k0 + tx] =
                __float2bfloat16(tile[tx][jl]);
        }
        return;
    }
    // ---- ln1 + Q projection, j-split: block = 8 rows x 256 q-cols ----
    __shared__ float xs[8][256];
    int lane = t & 31, w = t >> 5;
    int rg = bid >> 1, jh = bid & 1;
    int r0 = rg * 8;
    {
        int row = r0 + w;
        float v[8];
        float sum = 0.f;
#pragma unroll
        for (int i = 0; i < 8; i++) { v[i] = slots[(size_t)row * 256 + lane + 32 * i]; sum += v[i]; }
#pragma unroll
        for (int off = 16; off; off >>= 1) sum += __shfl_xor_sync(0xffffffffu, sum, off);
        float mean = sum * (1.f / 256.f);
        float vs = 0.f;
#pragma unroll
        for (int i = 0; i < 8; i++) { float d = v[i] - mean; vs += d * d; }
#pragma unroll
        for (int off = 16; off; off >>= 1) vs += __shfl_xor_sync(0xffffffffu, vs, off);
        float inv = rsqrtf(vs * (1.f / 256.f) + 1e-5f);
#pragma unroll
        for (int i = 0; i < 8; i++) {
            int c = lane + 32 * i;
            xs[w][c] = (v[i] - mean) * inv * g1[c] + be1[c];
        }
    }
    __syncthreads();
    int j = jh * 256 + t;
    float acc[8] = {};
    for (int kk0 = 0; kk0 < 256; kk0 += 8) {
        float wv[8];
#pragma unroll
        for (int u = 0; u < 8; u++) wv[u] = Wq[(kk0 + u) * 512 + j];
#pragma unroll
        for (int u = 0; u < 8; u++)
#pragma unroll
            for (int r = 0; r < 8; r++) acc[r] += xs[r][kk0 + u] * wv[u];
    }
    int h0 = j >> 6, d0 = j & 63;
#pragma unroll
    for (int r = 0; r < 8; r++) {
        int row = r0 + r, b = row >> 6, k = row & 63;
        g_q[(((size_t)b * HH + h0) * 64 + k) * 64 + d0] = __float2bfloat16(acc[r] * QSCALE);
    }
}

// ======= fused: KV-projection + flash attention (2 barriers/chunk) =======
// 152 CTAs: split s gets chunks [start, start+cnt), cnt = 7 (s<14) or 6.
__global__ void __launch_bounds__(256, 1) fused_attn() {
    extern __shared__ char smraw[];
    FS& sm = *reinterpret_cast<FS*>(smraw);

    const int s = blockIdx.x, b = blockIdx.y;
    const int tid = threadIdx.x, lane = tid & 31, warp = tid >> 5;
    const int wm = (warp >> 1) * 32, wn = (warp & 1) * 32;  // projection tiling
    const int p = warp & 3, hf = warp >> 2;                  // attention tiling
    const int g = lane >> 2, t4 = lane & 3;

    const int cnt = (s < 14) ? 7 : 6;
    const int start = (s < 14) ? s * 7 : 98 + (s - 14) * 6;
    const size_t cta_row0 = (size_t)b * NN + (size_t)start * CH;

    auto issueH = [&](int c) {
        const __nv_bfloat16* src = g_hits + (cta_row0 + (size_t)c * CH) * 256;
#pragma unroll
        for (int i = 0; i < 16; i++) {
            int idx = tid + 256 * i;
            int row = idx >> 5, seg = (idx & 31) * 8;
            cpasync16(sm.Hs + row * 264 + seg, src + (size_t)row * 256 + seg);
        }
        cpcommit();
    };
    auto issueW = [&](int h) {
#pragma unroll
        for (int i = 0; i < 8; i++) {
            int idx = tid + 256 * i;
            int row = idx >> 5, seg = (idx & 31) * 8;
            cpasync16(sm.Wks + row * 264 + seg, g_Wkvt + (size_t)(h * 64 + row) * 256 + seg);
            cpasync16(sm.Wvs + row * 264 + seg, g_Wkvt + (size_t)(512 + h * 64 + row) * 256 + seg);
        }
        cpcommit();
    };

    issueW(0);
    issueH(0);

    float mrow[2], lrow[2], oacc[8][4];
    uint32_t qa[4][4];

    for (int h = 0; h < HH; h++) {
        const int bh = b * HH + h;
        for (int c = 0; c < cnt; c++) {
            cpwait0();
            __syncthreads();                     // (1) H/W ready; prev attn done with KV

            // -------- projection: [K|V][128x64] = H[128x256] @ W^T --------
            float kacc[2][4][4] = {}, vacc[2][4][4] = {};
#pragma unroll
            for (int ks = 0; ks < 16; ks++) {
                uint32_t af[2][4];
#pragma unroll
                for (int mi = 0; mi < 2; mi++)
                    ldsm4(af[mi], sm.Hs + (wm + mi * 16 + (lane & 15)) * 264 + ks * 16 + (lane >> 4) * 8);
#pragma unroll
                for (int nb = 0; nb < 2; nb++) {
                    int nrow = wn + nb * 16 + (lane & 7) + ((lane >> 4) << 3);
                    uint32_t bf[4], cf[4];
                    ldsm4(bf, sm.Wks + nrow * 264 + ks * 16 + (lane & 8));
                    mma16816(kacc[0][2 * nb],     af[0], bf[0], bf[1]);
                    mma16816(kacc[0][2 * nb + 1], af[0], bf[2], bf[3]);
                    mma16816(kacc[1][2 * nb],     af[1], bf[0], bf[1]);
                    mma16816(kacc[1][2 * nb + 1], af[1], bf[2], bf[3]);
                    ldsm4(cf, sm.Wvs + nrow * 264 + ks * 16 + (lane & 8));
                    mma16816(vacc[0][2 * nb],     af[0], cf[0], cf[1]);
                    mma16816(vacc[0][2 * nb + 1], af[0], cf[2], cf[3]);
                    mma16816(vacc[1][2 * nb],     af[1], cf[0], cf[1]);
                    mma16816(vacc[1][2 * nb + 1], af[1], cf[2], cf[3]);
                }
            }

            // epilogue -> bf16 K/V smem tiles (scalar STS.32: conflict-free)
#pragma unroll
            for (int mi = 0; mi < 2; mi++) {
                int row = wm + mi * 16 + g;
#pragma unroll
                for (int nj = 0; nj < 4; nj++) {
                    int col = wn + nj * 8 + 2 * t4;
                    *(uint32_t*)&sm.Ks[row * 72 + col]       = packbf(kacc[mi][nj][0], kacc[mi][nj][1]);
                    *(uint32_t*)&sm.Ks[(row + 8) * 72 + col] = packbf(kacc[mi][nj][2], kacc[mi][nj][3]);
                    *(uint32_t*)&sm.Vs[row * 72 + col]       = packbf(vacc[mi][nj][0], vacc[mi][nj][1]);
                    *(uint32_t*)&sm.Vs[(row + 8) * 72 + col] = packbf(vacc[mi][nj][2], vacc[mi][nj][3]);
                }
            }
            __syncthreads();                     // (2) proj reads done + KV visible

            if (!(h == HH - 1 && c == cnt - 1)) {    // overlaps attention below
                if (c == cnt - 1) issueW(h + 1);
                issueH((c == cnt - 1) ? 0 : c + 1);
            }

            if (c == 0) {                        // Q frags direct from gmem; reset state
                const uint32_t* qp = (const uint32_t*)(g_q + (size_t)bh * 4096);
                int rq = p * 16 + g;
#pragma unroll
                for (int ks = 0; ks < 4; ks++) {
                    int cb = ks * 16 + t4 * 2;
                    qa[ks][0] = qp[(rq * 64 + cb) >> 1];
                    qa[ks][1] = qp[((rq + 8) * 64 + cb) >> 1];
                    qa[ks][2] = qp[(rq * 64 + cb + 8) >> 1];
                    qa[ks][3] = qp[((rq + 8) * 64 + cb + 8) >> 1];
                }
                mrow[0] = mrow[1] = -1e30f;
                lrow[0] = lrow[1] = 0.f;
#pragma unroll
                for (int dt = 0; dt < 8; dt++)
#pragma unroll
                    for (int r = 0; r < 4; r++) oacc[dt][r] = 0.f;
            }

            // -------- attention: QK^T over this warp's n-half --------
            float sacc[8][4] = {};
#pragma unroll
            for (int ks = 0; ks < 4; ks++) {
#pragma unroll
                for (int np = 0; np < 4; np++) {
                    int nrow = hf * 64 + np * 16 + (lane & 7) + ((lane >> 4) << 3);
                    uint32_t bf[4];
                    ldsm4(bf, sm.Ks + nrow * 72 + ks * 16 + (lane & 8));
                    mma16816(sacc[2 * np],     qa[ks], bf[0], bf[1]);
                    mma16816(sacc[2 * np + 1], qa[ks], bf[2], bf[3]);
                }
            }
            // -------- independent in-warp online softmax (log2 domain) --------
#pragma unroll
            for (int r = 0; r < 2; r++) {
                float m = -1e30f;
#pragma unroll
                for (int nt = 0; nt < 8; nt++)
                    m = fmaxf(m, fmaxf(sacc[nt][2 * r], sacc[nt][2 * r + 1]));
                m = fmaxf(m, __shfl_xor_sync(0xffffffffu, m, 1));
                m = fmaxf(m, __shfl_xor_sync(0xffffffffu, m, 2));
                float mnew = fmaxf(mrow[r], m);
                float sc = exp2f(mrow[r] - mnew);
                mrow[r] = mnew;
                float sum = 0.f;
#pragma unroll
                for (int nt = 0; nt < 8; nt++) {
                    float p0 = exp2f(sacc[nt][2 * r] - mnew);
                    float p1 = exp2f(sacc[nt][2 * r + 1] - mnew);
                    sacc[nt][2 * r] = p0; sacc[nt][2 * r + 1] = p1;
                    sum += p0 + p1;
                }
                sum += __shfl_xor_sync(0xffffffffu, sum, 1);
                sum += __shfl_xor_sync(0xffffffffu, sum, 2);
                lrow[r] = lrow[r] * sc + sum;
#pragma unroll
                for (int dt = 0; dt < 8; dt++) {
                    oacc[dt][2 * r] *= sc; oacc[dt][2 * r + 1] *= sc;
                }
            }
            // -------- P @ V over this n-half --------
            uint32_t pf[4][4];
#pragma unroll
            for (int k2 = 0; k2 < 4; k2++) {
                pf[k2][0] = packbf(sacc[2 * k2][0],     sacc[2 * k2][1]);
                pf[k2][1] = packbf(sacc[2 * k2][2],     sacc[2 * k2][3]);
                pf[k2][2] = packbf(sacc[2 * k2 + 1][0], sacc[2 * k2 + 1][1]);
                pf[k2][3] = packbf(sacc[2 * k2 + 1][2], sacc[2 * k2 + 1][3]);
            }
#pragma unroll
            for (int k2 = 0; k2 < 4; k2++) {
#pragma unroll
                for (int dp = 0; dp < 4; dp++) {
                    uint32_t vf[4];
                    ldsm4t(vf, sm.Vs + (hf * 64 + k2 * 16 + (lane & 15)) * 72
                                + dp * 16 + (lane >> 4) * 8);
                    mma16816(oacc[2 * dp],     pf[k2], vf[0], vf[1]);
                    mma16816(oacc[2 * dp + 1], pf[k2], vf[2], vf[3]);
                }
            }

            // -------- head end: each hf half writes its OWN split partial --------
            if (c == cnt - 1) {
                const int base = (bh * NPART + hf * NSPL + s) * 64;
                const int r0 = p * 16 + g;
#pragma unroll
                for (int dt = 0; dt < 8; dt++) {
                    int col = dt * 8 + 2 * t4;
                    *(float2*)&g_po[(size_t)(base + r0) * 64 + col] =
                        make_float2(oacc[dt][0], oacc[dt][1]);
                    *(float2*)&g_po[(size_t)(base + r0 + 8) * 64 + col] =
                        make_float2(oacc[dt][2], oacc[dt][3]);
                }
                if (t4 == 0) {
                    g_pm[base + r0] = mrow[0]; g_pm[base + r0 + 8] = mrow[1];
                    g_pl[base + r0] = lrow[0]; g_pl[base + r0 + 8] = lrow[1];
                }
            }
        }
    }
}

// ================= combine(38 splits) + MLP + residual + LN2 =====================
__global__ void __launch_bounds__(256) mlp_ln2(const float* __restrict__ slots,
                                               const float* __restrict__ W1,
                                               const float* __restrict__ b1,
                                               const float* __restrict__ W2,
                                               const float* __restrict__ b2,
                                               const float* __restrict__ g2,
                                               const float* __restrict__ be2,
                                               float* __restrict__ out) {
    __shared__ float av[MLPR][512];
    __shared__ float hid[MLPR][512];
    __shared__ float red[256];
    int t = threadIdx.x;
    int r0 = blockIdx.x * MLPR;
#pragma unroll
    for (int r = 0; r < MLPR; r++) {
        int row = r0 + r, bB = row >> 6, kk = row & 63;
#pragma unroll
        for (int jj = 0; jj < 2; jj++) {
            int d = t + 256 * jj;
            int h = d >> 6, dd = d & 63;
            int bh = bB * 8 + h;
            float M = -1e30f;
#pragma unroll
            for (int ss = 0; ss < NPART; ss++)
                M = fmaxf(M, g_pm[(bh * NPART + ss) * 64 + kk]);
            float L = 0.f, acc = 0.f;
#pragma unroll
            for (int ss = 0; ss < NPART; ss++) {
                int idx = (bh * NPART + ss) * 64 + kk;
                float w = exp2f(g_pm[idx] - M);
                L   += g_pl[idx] * w;
                acc += g_po[(size_t)idx * 64 + dd] * w;
            }
            av[r][d] = acc / L;
        }
    }
    __syncthreads();
    float a0[MLPR], a1[MLPR];
    float bb0 = b1[t], bb1 = b1[t + 256];
#pragma unroll
    for (int r = 0; r < MLPR; r++) { a0[r] = bb0; a1[r] = bb1; }
    for (int kk0 = 0; kk0 < 512; kk0 += 4) {
        float w0v[4], w1v[4];
#pragma unroll
        for (int u = 0; u < 4; u++) {
            w0v[u] = W1[(kk0 + u) * 512 + t];
            w1v[u] = W1[(kk0 + u) * 512 + t + 256];
        }
#pragma unroll
        for (int u = 0; u < 4; u++)
#pragma unroll
            for (int r = 0; r < MLPR; r++) {
                float x = av[r][kk0 + u];
                a0[r] += x * w0v[u]; a1[r] += x * w1v[u];
            }
    }
#pragma unroll
    for (int r = 0; r < MLPR; r++) {
        hid[r][t] = fmaxf(a0[r], 0.f);
        hid[r][t + 256] = fmaxf(a1[r], 0.f);
    }
    __syncthreads();
    float o[MLPR];
    float c0 = b2[t];
#pragma unroll
    for (int r = 0; r < MLPR; r++) o[r] = c0;
    for (int kk0 = 0; kk0 < 512; kk0 += 4) {
        float wv[4];
#pragma unroll
        for (int u = 0; u < 4; u++) wv[u] = W2[(kk0 + u) * 256 + t];
#pragma unroll
        for (int u = 0; u < 4; u++)
#pragma unroll
            for (int r = 0; r < MLPR; r++) o[r] += hid[r][kk0 + u] * wv[u];
    }
    float gg = g2[t], bbn = be2[t];
    for (int r = 0; r < MLPR; r++) {
        float x = slots[(size_t)(r0 + r) * 256 + t] + o[r];
        red[t] = x; __syncthreads();
        for (int off = 128; off; off >>= 1) { if (t < off) red[t] += red[t + off]; __syncthreads(); }
        float mean = red[0] * (1.f / 256.f); __syncthreads();
        float d = x - mean;
        red[t] = d * d; __syncthreads();
        for (int off = 128; off; off >>= 1) { if (t < off) red[t] += red[t + off]; __syncthreads(); }
        float var = red[0] * (1.f / 256.f); __syncthreads();
        out[(size_t)(r0 + r) * 256 + t] = d * rsqrtf(var + 1e-5f) * gg + bbn;
    }
}

extern "C" void kernel_launch(void* const* d_in, const int* in_sizes, int n_in,
                              void* d_out, int out_size) {
    const float* slots = (const float*)d_in[0];
    const float* hits  = (const float*)d_in[1];
    const float* ln1g  = (const float*)d_in[2];
    const float* ln1b  = (const float*)d_in[3];
    const float* Wq    = (const float*)d_in[4];
    const float* Wk    = (const float*)d_in[5];
    const float* Wv    = (const float*)d_in[6];
    const float* W1    = (const float*)d_in[7];
    const float* b1    = (const float*)d_in[8];
    const float* W2    = (const float*)d_in[9];
    const float* b2    = (const float*)d_in[10];
    const float* ln2g  = (const float*)d_in[11];
    const float* ln2b  = (const float*)d_in[12];
    float* out = (float*)d_out;

    cudaFuncSetAttribute(fused_attn, cudaFuncAttributeMaxDynamicSharedMemorySize,
                         (int)sizeof(FS));
    // grid: 128 ln1_q (j-split) + 256 transpose + 8192 cvt
    prep_all<<<8576, 256>>>((const float4*)hits, Wk, Wv, slots, ln1g, ln1b, Wq);
    fused_attn<<<dim3(NSPL, BB), 256, sizeof(FS)>>>();
    mlp_ln2<<<BB * KSLOT / MLPR, 256>>>(slots, W1, b1, W2, b2, ln2g, ln2b, out);
}